// round 1
// baseline (speedup 1.0000x reference)
#include <cuda_runtime.h>

// DilateAttention: B=8, d=768, N=6144, head_dim=32, kernel_size=3
// h=24 heads, g=2048 windows, 393216 independent 3x3 attentions over 32 dims.
// Pure HBM-streaming problem: 604 MB total traffic, ~95us roofline.
//
// Thread -> one (b,h,gi) window. Lanes vary gi -> all q/k/v loads are fully
// coalesced 128B. Output chunk (96 contiguous floats per thread, but 9216B
// apart across lanes) is staged in rotation-swizzled shared memory and then
// written with a coalesced flat loop.

namespace {
constexpr int G   = 2048;   // windows per (b,h)
constexpr int NH  = 24;     // heads
constexpr int HD  = 32;     // head_dim
constexpr int NN  = 6144;   // sequence length
constexpr int DD  = 768;    // model dim
constexpr int TPB = 128;    // threads (=windows) per block; 2048 % 128 == 0
constexpr int NWIN = 8 * NH * G;  // 393216 windows total
}

__global__ __launch_bounds__(TPB, 4)
void dilate_attn_kernel(const float* __restrict__ q,
                        const float* __restrict__ kin,
                        const float* __restrict__ v,
                        float* __restrict__ out)
{
    // 128 threads x 96 floats, rotation-swizzled: phys(t, idx) = t*96 + (idx+t)%96.
    // Write phase: lane t writes idx -> bank (idx+t)%32, all distinct. Conflict-free.
    // Read phase: lane reads (chunk c, within w) -> consecutive w -> consecutive
    // banks. Conflict-free. Exactly 48KB static smem.
    __shared__ float s[TPB * 96];

    const int t  = threadIdx.x;
    const int wt = blockIdx.x * TPB + t;     // global window id
    const int gi = wt & (G - 1);
    const int bh = wt >> 11;                 // 2048 = 2^11
    const int h  = bh % NH;
    const int b  = bh / NH;

    // q[b, h*32+hd, k*2048+gi]; channel stride NN, window-element stride G
    const int base = (b * DD + h * HD) * NN + gi;
    const float* qp = q   + base;
    const float* kp = kin + base;

    // ---- attn logits: 9 dot products over hd (streaming, coalesced loads) ----
    float a00=0.f,a01=0.f,a02=0.f,a10=0.f,a11=0.f,a12=0.f,a20=0.f,a21=0.f,a22=0.f;
#pragma unroll
    for (int c = 0; c < HD; ++c) {
        const int off = c * NN;
        float q0 = qp[off], q1 = qp[off + G], q2 = qp[off + 2 * G];
        float k0 = kp[off], k1 = kp[off + G], k2 = kp[off + 2 * G];
        a00 = fmaf(q0, k0, a00); a01 = fmaf(q0, k1, a01); a02 = fmaf(q0, k2, a02);
        a10 = fmaf(q1, k0, a10); a11 = fmaf(q1, k1, a11); a12 = fmaf(q1, k2, a12);
        a20 = fmaf(q2, k0, a20); a21 = fmaf(q2, k1, a21); a22 = fmaf(q2, k2, a22);
    }

    // ---- softmax over each 3-row (scale applied before softmax) ----
    const float sc = 0.17677669529663687f;  // 1/sqrt(32)
    float m0 = fmaxf(fmaxf(a00, a01), a02);
    float m1 = fmaxf(fmaxf(a10, a11), a12);
    float m2 = fmaxf(fmaxf(a20, a21), a22);
    float e00 = __expf((a00 - m0) * sc), e01 = __expf((a01 - m0) * sc), e02 = __expf((a02 - m0) * sc);
    float e10 = __expf((a10 - m1) * sc), e11 = __expf((a11 - m1) * sc), e12 = __expf((a12 - m1) * sc);
    float e20 = __expf((a20 - m2) * sc), e21 = __expf((a21 - m2) * sc), e22 = __expf((a22 - m2) * sc);
    float r0 = 1.f / (e00 + e01 + e02);
    float r1 = 1.f / (e10 + e11 + e12);
    float r2 = 1.f / (e20 + e21 + e22);
    float p00 = e00 * r0, p01 = e01 * r0, p02 = e02 * r0;
    float p10 = e10 * r1, p11 = e11 * r1, p12 = e12 * r1;
    float p20 = e20 * r2, p21 = e21 * r2, p22 = e22 * r2;

    // ---- output = attn @ v, staged into swizzled smem ----
    const float* vp = v + base;
    float* sp = s + t * 96;
#pragma unroll
    for (int c = 0; c < HD; ++c) {
        const int off = c * NN;
        float v0 = vp[off], v1 = vp[off + G], v2 = vp[off + 2 * G];
        float o0 = fmaf(p00, v0, fmaf(p01, v1, p02 * v2));
        float o1 = fmaf(p10, v0, fmaf(p11, v1, p12 * v2));
        float o2 = fmaf(p20, v0, fmaf(p21, v1, p22 * v2));
        // idx = k*32 + c, rotated by t (mod 96)
        int i0 = c + t;   if (i0 >= 96) i0 -= 96;
        int i1 = i0 + 32; if (i1 >= 96) i1 -= 96;
        int i2 = i1 + 32; if (i2 >= 96) i2 -= 96;
        sp[i0] = o0;
        sp[i1] = o1;
        sp[i2] = o2;
    }
    __syncthreads();

    // ---- coalesced writeback ----
    // chunk c (= producer thread) -> out row b*NN + 3*(gi0+c) + h/8, col (h%8)*96 + within.
    // b,h uniform across the block (2048 % 128 == 0).
    const int gi0 = (blockIdx.x * TPB) & (G - 1);
    float* ob = out + ((size_t)(b * NN + gi0 * 3 + (h >> 3))) * DD + (h & 7) * 96;
#pragma unroll 4
    for (int i = t; i < TPB * 96; i += TPB) {
        int c = i / 96;
        int w = i - c * 96;
        int ph = w + c;
        if (ph >= 96) ph -= 96;
        if (ph >= 96) ph -= 96;   // c up to 127: w+c can exceed 192
        ob[c * (3 * DD) + w] = s[c * 96 + ph];
    }
}

extern "C" void kernel_launch(void* const* d_in, const int* in_sizes, int n_in,
                              void* d_out, int out_size)
{
    const float* q = (const float*)d_in[0];
    const float* k = (const float*)d_in[1];
    const float* v = (const float*)d_in[2];
    float* out = (float*)d_out;
    dilate_attn_kernel<<<NWIN / TPB, TPB>>>(q, k, v, out);
}